// round 1
// baseline (speedup 1.0000x reference)
#include <cuda_runtime.h>
#include <math.h>

#define SQ 4096
#define DM 1024
#define NH 16
#define DHD 64
#define FF 4096

// Scratch (device globals — no runtime allocation allowed)
__device__ float g_y  [SQ*DM];   // LN1 output
__device__ float g_q  [SQ*DM];
__device__ float g_k  [SQ*DM];
__device__ float g_v  [SQ*DM];
__device__ float g_ctx[SQ*DM];
__device__ float g_y2 [SQ*DM];   // LN2 output
__device__ float g_h  [SQ*FF];   // GELU(ffn1) output

// ---------------------------------------------------------------------------
// LayerNorm: one block per row, 256 threads, D=1024 (4 elems/thread)
// ---------------------------------------------------------------------------
__global__ __launch_bounds__(256) void ln_kernel(const float* __restrict__ x,
                                                 const float* __restrict__ sc,
                                                 const float* __restrict__ bi,
                                                 float* __restrict__ y)
{
    int row = blockIdx.x;
    const float* xr = x + (size_t)row * DM;
    int t = threadIdx.x;

    float v[4];
    float s = 0.f;
#pragma unroll
    for (int i = 0; i < 4; i++) { v[i] = xr[t + i * 256]; s += v[i]; }

    __shared__ float red[8];
#pragma unroll
    for (int o = 16; o > 0; o >>= 1) s += __shfl_xor_sync(0xffffffffu, s, o);
    if ((t & 31) == 0) red[t >> 5] = s;
    __syncthreads();
    float tot = 0.f;
    if (t < 32) {
        float r = (t < 8) ? red[t] : 0.f;
#pragma unroll
        for (int o = 4; o > 0; o >>= 1) r += __shfl_xor_sync(0xffffffffu, r, o);
        if (t == 0) red[0] = r;
    }
    __syncthreads();
    float mu = red[0] * (1.0f / DM);
    __syncthreads();   // everyone has read red[0] before reuse

    float vs = 0.f;
#pragma unroll
    for (int i = 0; i < 4; i++) { float d = v[i] - mu; vs += d * d; }
#pragma unroll
    for (int o = 16; o > 0; o >>= 1) vs += __shfl_xor_sync(0xffffffffu, vs, o);
    if ((t & 31) == 0) red[t >> 5] = vs;
    __syncthreads();
    if (t < 32) {
        float r = (t < 8) ? red[t] : 0.f;
#pragma unroll
        for (int o = 4; o > 0; o >>= 1) r += __shfl_xor_sync(0xffffffffu, r, o);
        if (t == 0) red[0] = r;
    }
    __syncthreads();
    float var = red[0] * (1.0f / DM);
    float rstd = rsqrtf(var + 1e-6f);

    float* yr = y + (size_t)row * DM;
#pragma unroll
    for (int i = 0; i < 4; i++) {
        int c = t + i * 256;
        yr[c] = (v[i] - mu) * rstd * sc[c] + bi[c];
    }
}

// ---------------------------------------------------------------------------
// Tiled fp32 GEMM: C[M,N] = epi(A[M,K] @ B[K,N] + bias[N] [+ R])
// BM=BN=64, BK=16, 256 threads, 4x4 per thread.
// EPI: 0 = bias; 1 = bias + residual; 2 = bias + exact GELU
// ---------------------------------------------------------------------------
template <int EPI>
__global__ __launch_bounds__(256) void gemm_kernel(const float* __restrict__ A,
                                                   const float* __restrict__ B,
                                                   const float* __restrict__ bias,
                                                   const float* __restrict__ R,
                                                   float* __restrict__ C,
                                                   int M, int N, int K)
{
    __shared__ float As[16][65];   // transposed A tile: As[k][row], +1 pad
    __shared__ float Bs[16][64];   // Bs[k][col]

    const int bx = blockIdx.x, by = blockIdx.y;
    const int t = threadIdx.x;
    const int tx = t & 15, ty = t >> 4;
    const int row0 = by * 64, col0 = bx * 64;

    const int lkA = t & 15;   // k within A tile
    const int lrA = t >> 4;   // row base (0..15)
    const int lcB = t & 63;   // col within B tile
    const int lkB = t >> 6;   // k base (0..3)

    float c[4][4] = {};

    for (int k0 = 0; k0 < K; k0 += 16) {
#pragma unroll
        for (int it = 0; it < 4; it++) {
            int r = lrA + it * 16;
            As[lkA][r] = A[(size_t)(row0 + r) * K + k0 + lkA];
        }
#pragma unroll
        for (int it = 0; it < 4; it++) {
            int kk = lkB + it * 4;
            Bs[kk][lcB] = B[(size_t)(k0 + kk) * N + col0 + lcB];
        }
        __syncthreads();
#pragma unroll
        for (int kk = 0; kk < 16; kk++) {
            float a[4], b[4];
#pragma unroll
            for (int i = 0; i < 4; i++) a[i] = As[kk][ty * 4 + i];
#pragma unroll
            for (int j = 0; j < 4; j++) b[j] = Bs[kk][tx * 4 + j];
#pragma unroll
            for (int i = 0; i < 4; i++)
#pragma unroll
                for (int j = 0; j < 4; j++)
                    c[i][j] = fmaf(a[i], b[j], c[i][j]);
        }
        __syncthreads();
    }

#pragma unroll
    for (int i = 0; i < 4; i++) {
        int rg = row0 + ty * 4 + i;
#pragma unroll
        for (int j = 0; j < 4; j++) {
            int cg = col0 + tx * 4 + j;
            size_t idx = (size_t)rg * N + cg;
            float val = c[i][j] + bias[cg];
            if (EPI == 1) val += R[idx];
            if (EPI == 2) val = 0.5f * val * (1.0f + erff(val * 0.70710678118654752f));
            C[idx] = val;
        }
    }
}

// ---------------------------------------------------------------------------
// Flash attention (fp32, online softmax). Block = (q-tile of 64 rows, head).
// 256 threads; smem: Qs[64][65] + KVs[64][65] (K then V) + Ps[64][65].
// ---------------------------------------------------------------------------
#define ATTN_SMEM_FLOATS (3 * 64 * 65)
#define ATTN_SMEM_BYTES  (ATTN_SMEM_FLOATS * 4)

__global__ __launch_bounds__(256) void attn_kernel(const float* __restrict__ q,
                                                   const float* __restrict__ k,
                                                   const float* __restrict__ v,
                                                   float* __restrict__ ctx)
{
    extern __shared__ float sm[];
    float* Qs  = sm;               // [64][65]
    float* KVs = sm + 64 * 65;     // [64][65] — K, then reused for V
    float* Ps  = sm + 2 * 64 * 65; // [64][65]

    const int h  = blockIdx.y;
    const int q0 = blockIdx.x * 64;
    const int t  = threadIdx.x;
    const int tx = t & 15, ty = t >> 4;

    // Load Q tile, pre-scaled by 1/sqrt(DH) = 0.125
#pragma unroll
    for (int it = 0; it < 16; it++) {
        int idx = t + it * 256;
        int r = idx >> 6, c = idx & 63;
        Qs[r * 65 + c] = q[(size_t)(q0 + r) * DM + h * DHD + c] * 0.125f;
    }

    float acc[4][4] = {};
    float m_i[4], l_i[4];
#pragma unroll
    for (int i = 0; i < 4; i++) { m_i[i] = -1e30f; l_i[i] = 0.f; }
    __syncthreads();

    for (int kb = 0; kb < SQ / 64; kb++) {
        const int k0 = kb * 64;

        // load K tile
#pragma unroll
        for (int it = 0; it < 16; it++) {
            int idx = t + it * 256;
            int r = idx >> 6, c = idx & 63;
            KVs[r * 65 + c] = k[(size_t)(k0 + r) * DM + h * DHD + c];
        }
        __syncthreads();

        // S = Q @ K^T  (each thread: 4 q-rows x 4 k-rows)
        float s[4][4] = {};
#pragma unroll 8
        for (int c = 0; c < 64; c++) {
            float a[4], b[4];
#pragma unroll
            for (int i = 0; i < 4; i++) a[i] = Qs[(ty * 4 + i) * 65 + c];
#pragma unroll
            for (int j = 0; j < 4; j++) b[j] = KVs[(tx * 4 + j) * 65 + c];
#pragma unroll
            for (int i = 0; i < 4; i++)
#pragma unroll
                for (int j = 0; j < 4; j++)
                    s[i][j] = fmaf(a[i], b[j], s[i][j]);
        }

        // online softmax update (row group = 16 tx threads; xor<=8 stays in group)
#pragma unroll
        for (int i = 0; i < 4; i++) {
            float mx = fmaxf(fmaxf(s[i][0], s[i][1]), fmaxf(s[i][2], s[i][3]));
#pragma unroll
            for (int o = 8; o > 0; o >>= 1) mx = fmaxf(mx, __shfl_xor_sync(0xffffffffu, mx, o));
            float mnew  = fmaxf(m_i[i], mx);
            float alpha = __expf(m_i[i] - mnew);
            float rs = 0.f;
#pragma unroll
            for (int j = 0; j < 4; j++) { s[i][j] = __expf(s[i][j] - mnew); rs += s[i][j]; }
#pragma unroll
            for (int o = 8; o > 0; o >>= 1) rs += __shfl_xor_sync(0xffffffffu, rs, o);
            l_i[i] = l_i[i] * alpha + rs;
            m_i[i] = mnew;
#pragma unroll
            for (int j = 0; j < 4; j++) acc[i][j] *= alpha;
#pragma unroll
            for (int j = 0; j < 4; j++) Ps[(ty * 4 + i) * 65 + tx * 4 + j] = s[i][j];
        }
        __syncthreads();   // Ps ready; done reading K

        // load V tile into same buffer
#pragma unroll
        for (int it = 0; it < 16; it++) {
            int idx = t + it * 256;
            int r = idx >> 6, c = idx & 63;
            KVs[r * 65 + c] = v[(size_t)(k0 + r) * DM + h * DHD + c];
        }
        __syncthreads();

        // acc += P @ V
#pragma unroll 8
        for (int kk = 0; kk < 64; kk++) {
            float a[4], b[4];
#pragma unroll
            for (int i = 0; i < 4; i++) a[i] = Ps[(ty * 4 + i) * 65 + kk];
#pragma unroll
            for (int j = 0; j < 4; j++) b[j] = KVs[kk * 65 + tx * 4 + j];
#pragma unroll
            for (int i = 0; i < 4; i++)
#pragma unroll
                for (int j = 0; j < 4; j++)
                    acc[i][j] = fmaf(a[i], b[j], acc[i][j]);
        }
        __syncthreads();   // before next tile overwrites KVs
    }

    // epilogue: normalize and store
#pragma unroll
    for (int i = 0; i < 4; i++) {
        float inv = 1.0f / l_i[i];
#pragma unroll
        for (int j = 0; j < 4; j++)
            ctx[(size_t)(q0 + ty * 4 + i) * DM + h * DHD + tx * 4 + j] = acc[i][j] * inv;
    }
}

// ---------------------------------------------------------------------------
extern "C" void kernel_launch(void* const* d_in, const int* in_sizes, int n_in,
                              void* d_out, int out_size)
{
    const float* x   = (const float*)d_in[0];
    const float* Wq  = (const float*)d_in[1];
    const float* bq  = (const float*)d_in[2];
    const float* Wk  = (const float*)d_in[3];
    const float* bk  = (const float*)d_in[4];
    const float* Wv  = (const float*)d_in[5];
    const float* bv  = (const float*)d_in[6];
    const float* Wo  = (const float*)d_in[7];
    const float* bo  = (const float*)d_in[8];
    const float* l1s = (const float*)d_in[9];
    const float* l1b = (const float*)d_in[10];
    const float* l2s = (const float*)d_in[11];
    const float* l2b = (const float*)d_in[12];
    const float* W1  = (const float*)d_in[13];
    const float* b1  = (const float*)d_in[14];
    const float* W2  = (const float*)d_in[15];
    const float* b2  = (const float*)d_in[16];
    float* out = (float*)d_out;

    float *py, *pq, *pk, *pv, *pctx, *py2, *ph;
    cudaGetSymbolAddress((void**)&py,   g_y);
    cudaGetSymbolAddress((void**)&pq,   g_q);
    cudaGetSymbolAddress((void**)&pk,   g_k);
    cudaGetSymbolAddress((void**)&pv,   g_v);
    cudaGetSymbolAddress((void**)&pctx, g_ctx);
    cudaGetSymbolAddress((void**)&py2,  g_y2);
    cudaGetSymbolAddress((void**)&ph,   g_h);

    cudaFuncSetAttribute(attn_kernel, cudaFuncAttributeMaxDynamicSharedMemorySize,
                         ATTN_SMEM_BYTES);

    // LN1
    ln_kernel<<<SQ, 256>>>(x, l1s, l1b, py);

    // QKV projections
    dim3 gDD(DM / 64, SQ / 64);
    gemm_kernel<0><<<gDD, 256>>>(py, Wq, bq, nullptr, pq, SQ, DM, DM);
    gemm_kernel<0><<<gDD, 256>>>(py, Wk, bk, nullptr, pk, SQ, DM, DM);
    gemm_kernel<0><<<gDD, 256>>>(py, Wv, bv, nullptr, pv, SQ, DM, DM);

    // Attention
    attn_kernel<<<dim3(SQ / 64, NH), 256, ATTN_SMEM_BYTES>>>(pq, pk, pv, pctx);

    // Output projection + residual  -> out holds x2 = x + attn_out
    gemm_kernel<1><<<gDD, 256>>>(pctx, Wo, bo, x, out, SQ, DM, DM);

    // LN2
    ln_kernel<<<SQ, 256>>>(out, l2s, l2b, py2);

    // FFN1 + GELU
    gemm_kernel<2><<<dim3(FF / 64, SQ / 64), 256>>>(py2, W1, b1, nullptr, ph, SQ, FF, DM);

    // FFN2 + residual (reads and writes `out` at the same element — safe,
    // each element is read once by the thread that writes it)
    gemm_kernel<1><<<gDD, 256>>>(ph, W2, b2, out, out, SQ, DM, FF);
}

// round 3
// speedup vs baseline: 1.3985x; 1.3985x over previous
#include <cuda_runtime.h>
#include <cuda_bf16.h>
#include <math.h>
#include <stdint.h>

#define SQ 4096
#define DM 1024
#define NH 16
#define DHD 64
#define FF 4096

// Scratch (device globals — no runtime allocation allowed)
__device__ float g_y  [SQ*DM];   // LN1 output
__device__ float g_q  [SQ*DM];
__device__ float g_k  [SQ*DM];
__device__ float g_v  [SQ*DM];
__device__ float g_ctx[SQ*DM];
__device__ float g_y2 [SQ*DM];   // LN2 output
__device__ float g_h  [SQ*FF];   // GELU(ffn1) output

// ===========================================================================
// Helpers
// ===========================================================================
__device__ __forceinline__ uint32_t smem_u32(const void* p) {
    uint32_t a;
    asm("{ .reg .u64 t; cvta.to.shared.u64 t, %1; cvt.u32.u64 %0, t; }" : "=r"(a) : "l"(p));
    return a;
}

__device__ __forceinline__ void ldsm4(uint32_t* r, uint32_t addr) {
    asm volatile("ldmatrix.sync.aligned.m8n8.x4.shared.b16 {%0,%1,%2,%3}, [%4];"
        : "=r"(r[0]), "=r"(r[1]), "=r"(r[2]), "=r"(r[3]) : "r"(addr));
}

__device__ __forceinline__ void mma16816(float* c, const uint32_t* a,
                                         uint32_t b0, uint32_t b1) {
    asm volatile("mma.sync.aligned.m16n8k16.row.col.f32.bf16.bf16.f32 "
        "{%0,%1,%2,%3}, {%4,%5,%6,%7}, {%8,%9}, {%0,%1,%2,%3};"
        : "+f"(c[0]), "+f"(c[1]), "+f"(c[2]), "+f"(c[3])
        : "r"(a[0]), "r"(a[1]), "r"(a[2]), "r"(a[3]), "r"(b0), "r"(b1));
}

__device__ __forceinline__ void split_pack(float x0, float x1, uint32_t& hp, uint32_t& lp) {
    __nv_bfloat16 h0 = __float2bfloat16_rn(x0);
    __nv_bfloat16 h1 = __float2bfloat16_rn(x1);
    __nv_bfloat16 l0 = __float2bfloat16_rn(x0 - __bfloat162float(h0));
    __nv_bfloat16 l1 = __float2bfloat16_rn(x1 - __bfloat162float(h1));
    hp = (uint32_t)__bfloat16_as_ushort(h0) | ((uint32_t)__bfloat16_as_ushort(h1) << 16);
    lp = (uint32_t)__bfloat16_as_ushort(l0) | ((uint32_t)__bfloat16_as_ushort(l1) << 16);
}

// ---------------------------------------------------------------------------
// LayerNorm: one block per row, 256 threads, D=1024 (4 elems/thread)
// ---------------------------------------------------------------------------
__global__ __launch_bounds__(256) void ln_kernel(const float* __restrict__ x,
                                                 const float* __restrict__ sc,
                                                 const float* __restrict__ bi,
                                                 float* __restrict__ y)
{
    int row = blockIdx.x;
    const float* xr = x + (size_t)row * DM;
    int t = threadIdx.x;

    float v[4];
    float s = 0.f;
#pragma unroll
    for (int i = 0; i < 4; i++) { v[i] = xr[t + i * 256]; s += v[i]; }

    __shared__ float red[8];
#pragma unroll
    for (int o = 16; o > 0; o >>= 1) s += __shfl_xor_sync(0xffffffffu, s, o);
    if ((t & 31) == 0) red[t >> 5] = s;
    __syncthreads();
    if (t < 32) {
        float r = (t < 8) ? red[t] : 0.f;
#pragma unroll
        for (int o = 4; o > 0; o >>= 1) r += __shfl_xor_sync(0xffffffffu, r, o);
        if (t == 0) red[0] = r;
    }
    __syncthreads();
    float mu = red[0] * (1.0f / DM);
    __syncthreads();

    float vs = 0.f;
#pragma unroll
    for (int i = 0; i < 4; i++) { float d = v[i] - mu; vs += d * d; }
#pragma unroll
    for (int o = 16; o > 0; o >>= 1) vs += __shfl_xor_sync(0xffffffffu, vs, o);
    if ((t & 31) == 0) red[t >> 5] = vs;
    __syncthreads();
    if (t < 32) {
        float r = (t < 8) ? red[t] : 0.f;
#pragma unroll
        for (int o = 4; o > 0; o >>= 1) r += __shfl_xor_sync(0xffffffffu, r, o);
        if (t == 0) red[0] = r;
    }
    __syncthreads();
    float var = red[0] * (1.0f / DM);
    float rstd = rsqrtf(var + 1e-6f);

    float* yr = y + (size_t)row * DM;
#pragma unroll
    for (int i = 0; i < 4; i++) {
        int c = t + i * 256;
        yr[c] = (v[i] - mu) * rstd * sc[c] + bi[c];
    }
}

// ---------------------------------------------------------------------------
// HMMA bf16-split GEMM: C[M,N] = epi(A[M,K] @ B[K,N] + bias[N] [+ R])
// Block tile 128x64, BK=32, 8 warps (4M x 2N), warp tile 32x32.
// A,B split hi/lo bf16; acc = Ah*Bh + Ah*Bl + Al*Bh in fp32 registers.
// smem: A [128][40] halfs (80B stride, 16B aligned rows), B [64][40] ([n][k]).
// EPI: 0=bias; 1=bias+residual; 2=bias+exact GELU
// ---------------------------------------------------------------------------
#define ASTRIDE 40   // halfwords; 80 bytes
template <int EPI>
__global__ __launch_bounds__(256, 2) void hmma_gemm(const float* __restrict__ A,
                                                    const float* __restrict__ B,
                                                    const float* __restrict__ bias,
                                                    const float* __restrict__ R,
                                                    float* __restrict__ C,
                                                    int M, int N, int K)
{
    __shared__ __align__(16) __nv_bfloat16 sAh[128 * ASTRIDE];
    __shared__ __align__(16) __nv_bfloat16 sAl[128 * ASTRIDE];
    __shared__ __align__(16) __nv_bfloat16 sBh[64 * ASTRIDE];
    __shared__ __align__(16) __nv_bfloat16 sBl[64 * ASTRIDE];

    const int t = threadIdx.x;
    const int lane = t & 31, w = t >> 5;
    const int wm = w & 3, wn = w >> 2;
    const int row0 = blockIdx.y * 128, col0 = blockIdx.x * 64;

    const uint32_t uAh = smem_u32(sAh), uAl = smem_u32(sAl);
    const uint32_t uBh = smem_u32(sBh), uBl = smem_u32(sBl);

    // ldmatrix per-lane byte offsets (add ks*32 for k-step)
    // A atoms i=0,1: rows wm*32 + i*16 + (lane&7) + 8*((lane>>3)&1); k = 8*(lane>>4)
    uint32_t aOff[2];
#pragma unroll
    for (int i = 0; i < 2; i++) {
        int r = wm * 32 + i * 16 + (lane & 7) + 8 * ((lane >> 3) & 1);
        aOff[i] = (uint32_t)(r * (ASTRIDE * 2) + 16 * (lane >> 4));
    }
    // B atom-pairs jj=0,1: n = wn*32 + jj*16 + (lane&7) + 8*(lane>>4); k = 8*((lane>>3)&1)
    uint32_t bOff[2];
#pragma unroll
    for (int jj = 0; jj < 2; jj++) {
        int n = wn * 32 + jj * 16 + (lane & 7) + 8 * (lane >> 4);
        bOff[jj] = (uint32_t)(n * (ASTRIDE * 2) + 16 * ((lane >> 3) & 1));
    }

    float acc[2][4][4] = {};

    // global load indices
    const int a_k2 = t & 15;          // float2 index within 32-k chunk
    const int a_m0 = t >> 4;          // 0..15
    const int b_n  = t & 63;
    const int b_g  = t >> 6;          // 0..3

    for (int k0 = 0; k0 < K; k0 += 32) {
        // --- A tile: 128 x 32 fp32 -> hi/lo bf16, [m][k] ---
#pragma unroll
        for (int it = 0; it < 8; it++) {
            int m = a_m0 + 16 * it;
            float2 a = *(const float2*)(A + (size_t)(row0 + m) * K + k0 + 2 * a_k2);
            uint32_t hp, lp;
            split_pack(a.x, a.y, hp, lp);
            uint32_t off = (uint32_t)(m * (ASTRIDE * 2) + a_k2 * 4);
            *(uint32_t*)((char*)sAh + off) = hp;
            *(uint32_t*)((char*)sAl + off) = lp;
        }
        // --- B tile: 32 x 64 fp32, transposed to [n][k] hi/lo bf16 ---
#pragma unroll
        for (int it = 0; it < 4; it++) {
            int kp = b_g + 4 * it;    // k-pair index 0..15
            float b0 = B[(size_t)(k0 + 2 * kp)     * N + col0 + b_n];
            float b1 = B[(size_t)(k0 + 2 * kp + 1) * N + col0 + b_n];
            uint32_t hp, lp;
            split_pack(b0, b1, hp, lp);
            uint32_t off = (uint32_t)(b_n * (ASTRIDE * 2) + kp * 4);
            *(uint32_t*)((char*)sBh + off) = hp;
            *(uint32_t*)((char*)sBl + off) = lp;
        }
        __syncthreads();

#pragma unroll
        for (int ks = 0; ks < 2; ks++) {
            const uint32_t kb = ks * 32;
            uint32_t ah[2][4], al[2][4], bh[2][4], bl[2][4];
#pragma unroll
            for (int i = 0; i < 2; i++) {
                ldsm4(ah[i], uAh + aOff[i] + kb);
                ldsm4(al[i], uAl + aOff[i] + kb);
            }
#pragma unroll
            for (int jj = 0; jj < 2; jj++) {
                ldsm4(bh[jj], uBh + bOff[jj] + kb);
                ldsm4(bl[jj], uBl + bOff[jj] + kb);
            }
#pragma unroll
            for (int i = 0; i < 2; i++)
#pragma unroll
                for (int j = 0; j < 4; j++) {
                    const int jj = j >> 1, e = (j & 1) * 2;
                    mma16816(acc[i][j], ah[i], bh[jj][e], bh[jj][e + 1]);
                    mma16816(acc[i][j], ah[i], bl[jj][e], bl[jj][e + 1]);
                    mma16816(acc[i][j], al[i], bh[jj][e], bh[jj][e + 1]);
                }
        }
        __syncthreads();
    }

    // --- epilogue ---
#pragma unroll
    for (int i = 0; i < 2; i++) {
#pragma unroll
        for (int j = 0; j < 4; j++) {
            int r = row0 + wm * 32 + i * 16 + (lane >> 2);
            int c = col0 + wn * 32 + j * 8 + 2 * (lane & 3);
#pragma unroll
            for (int half = 0; half < 2; half++) {
                int rr = r + half * 8;
                float2 v;
                v.x = acc[i][j][half * 2 + 0] + bias[c];
                v.y = acc[i][j][half * 2 + 1] + bias[c + 1];
                size_t idx = (size_t)rr * N + c;
                if (EPI == 1) {
                    float2 r2 = *(const float2*)(R + idx);
                    v.x += r2.x; v.y += r2.y;
                }
                if (EPI == 2) {
                    v.x = 0.5f * v.x * (1.0f + erff(v.x * 0.70710678118654752f));
                    v.y = 0.5f * v.y * (1.0f + erff(v.y * 0.70710678118654752f));
                }
                *(float2*)(C + idx) = v;
            }
        }
    }
}

// ---------------------------------------------------------------------------
// Flash attention (fp32, online softmax). Block = (q-tile of 64 rows, head).
// ---------------------------------------------------------------------------
#define ATTN_SMEM_FLOATS (3 * 64 * 65)
#define ATTN_SMEM_BYTES  (ATTN_SMEM_FLOATS * 4)

__global__ __launch_bounds__(256) void attn_kernel(const float* __restrict__ q,
                                                   const float* __restrict__ k,
                                                   const float* __restrict__ v,
                                                   float* __restrict__ ctx)
{
    extern __shared__ float sm[];
    float* Qs  = sm;
    float* KVs = sm + 64 * 65;
    float* Ps  = sm + 2 * 64 * 65;

    const int h  = blockIdx.y;
    const int q0 = blockIdx.x * 64;
    const int t  = threadIdx.x;
    const int tx = t & 15, ty = t >> 4;

#pragma unroll
    for (int it = 0; it < 16; it++) {
        int idx = t + it * 256;
        int r = idx >> 6, c = idx & 63;
        Qs[r * 65 + c] = q[(size_t)(q0 + r) * DM + h * DHD + c] * 0.125f;
    }

    float acc[4][4] = {};
    float m_i[4], l_i[4];
#pragma unroll
    for (int i = 0; i < 4; i++) { m_i[i] = -1e30f; l_i[i] = 0.f; }
    __syncthreads();

    for (int kb = 0; kb < SQ / 64; kb++) {
        const int k0 = kb * 64;

#pragma unroll
        for (int it = 0; it < 16; it++) {
            int idx = t + it * 256;
            int r = idx >> 6, c = idx & 63;
            KVs[r * 65 + c] = k[(size_t)(k0 + r) * DM + h * DHD + c];
        }
        __syncthreads();

        float s[4][4] = {};
#pragma unroll 8
        for (int c = 0; c < 64; c++) {
            float a[4], b[4];
#pragma unroll
            for (int i = 0; i < 4; i++) a[i] = Qs[(ty * 4 + i) * 65 + c];
#pragma unroll
            for (int j = 0; j < 4; j++) b[j] = KVs[(tx * 4 + j) * 65 + c];
#pragma unroll
            for (int i = 0; i < 4; i++)
#pragma unroll
                for (int j = 0; j < 4; j++)
                    s[i][j] = fmaf(a[i], b[j], s[i][j]);
        }

#pragma unroll
        for (int i = 0; i < 4; i++) {
            float mx = fmaxf(fmaxf(s[i][0], s[i][1]), fmaxf(s[i][2], s[i][3]));
#pragma unroll
            for (int o = 8; o > 0; o >>= 1) mx = fmaxf(mx, __shfl_xor_sync(0xffffffffu, mx, o));
            float mnew  = fmaxf(m_i[i], mx);
            float alpha = __expf(m_i[i] - mnew);
            float rs = 0.f;
#pragma unroll
            for (int j = 0; j < 4; j++) { s[i][j] = __expf(s[i][j] - mnew); rs += s[i][j]; }
#pragma unroll
            for (int o = 8; o > 0; o >>= 1) rs += __shfl_xor_sync(0xffffffffu, rs, o);
            l_i[i] = l_i[i] * alpha + rs;
            m_i[i] = mnew;
#pragma unroll
            for (int j = 0; j < 4; j++) acc[i][j] *= alpha;
#pragma unroll
            for (int j = 0; j < 4; j++) Ps[(ty * 4 + i) * 65 + tx * 4 + j] = s[i][j];
        }
        __syncthreads();

#pragma unroll
        for (int it = 0; it < 16; it++) {
            int idx = t + it * 256;
            int r = idx >> 6, c = idx & 63;
            KVs[r * 65 + c] = v[(size_t)(k0 + r) * DM + h * DHD + c];
        }
        __syncthreads();

#pragma unroll 8
        for (int kk = 0; kk < 64; kk++) {
            float a[4], b[4];
#pragma unroll
            for (int i = 0; i < 4; i++) a[i] = Ps[(ty * 4 + i) * 65 + kk];
#pragma unroll
            for (int j = 0; j < 4; j++) b[j] = KVs[kk * 65 + tx * 4 + j];
#pragma unroll
            for (int i = 0; i < 4; i++)
#pragma unroll
                for (int j = 0; j < 4; j++)
                    acc[i][j] = fmaf(a[i], b[j], acc[i][j]);
        }
        __syncthreads();
    }

#pragma unroll
    for (int i = 0; i < 4; i++) {
        float inv = 1.0f / l_i[i];
#pragma unroll
        for (int j = 0; j < 4; j++)
            ctx[(size_t)(q0 + ty * 4 + i) * DM + h * DHD + tx * 4 + j] = acc[i][j] * inv;
    }
}

// ---------------------------------------------------------------------------
extern "C" void kernel_launch(void* const* d_in, const int* in_sizes, int n_in,
                              void* d_out, int out_size)
{
    const float* x   = (const float*)d_in[0];
    const float* Wq  = (const float*)d_in[1];
    const float* bq  = (const float*)d_in[2];
    const float* Wk  = (const float*)d_in[3];
    const float* bk  = (const float*)d_in[4];
    const float* Wv  = (const float*)d_in[5];
    const float* bv  = (const float*)d_in[6];
    const float* Wo  = (const float*)d_in[7];
    const float* bo  = (const float*)d_in[8];
    const float* l1s = (const float*)d_in[9];
    const float* l1b = (const float*)d_in[10];
    const float* l2s = (const float*)d_in[11];
    const float* l2b = (const float*)d_in[12];
    const float* W1  = (const float*)d_in[13];
    const float* b1  = (const float*)d_in[14];
    const float* W2  = (const float*)d_in[15];
    const float* b2  = (const float*)d_in[16];
    float* out = (float*)d_out;

    float *py, *pq, *pk, *pv, *pctx, *py2, *ph;
    cudaGetSymbolAddress((void**)&py,   g_y);
    cudaGetSymbolAddress((void**)&pq,   g_q);
    cudaGetSymbolAddress((void**)&pk,   g_k);
    cudaGetSymbolAddress((void**)&pv,   g_v);
    cudaGetSymbolAddress((void**)&pctx, g_ctx);
    cudaGetSymbolAddress((void**)&py2,  g_y2);
    cudaGetSymbolAddress((void**)&ph,   g_h);

    cudaFuncSetAttribute(attn_kernel, cudaFuncAttributeMaxDynamicSharedMemorySize,
                         ATTN_SMEM_BYTES);

    // LN1
    ln_kernel<<<SQ, 256>>>(x, l1s, l1b, py);

    // QKV projections (HMMA bf16-split)
    dim3 gDD(DM / 64, SQ / 128);
    hmma_gemm<0><<<gDD, 256>>>(py, Wq, bq, nullptr, pq, SQ, DM, DM);
    hmma_gemm<0><<<gDD, 256>>>(py, Wk, bk, nullptr, pk, SQ, DM, DM);
    hmma_gemm<0><<<gDD, 256>>>(py, Wv, bv, nullptr, pv, SQ, DM, DM);

    // Attention (fp32 SIMT flash)
    attn_kernel<<<dim3(SQ / 64, NH), 256, ATTN_SMEM_BYTES>>>(pq, pk, pv, pctx);

    // Output projection + residual
    hmma_gemm<1><<<gDD, 256>>>(pctx, Wo, bo, x, out, SQ, DM, DM);

    // LN2
    ln_kernel<<<SQ, 256>>>(out, l2s, l2b, py2);

    // FFN1 + GELU
    hmma_gemm<2><<<dim3(FF / 64, SQ / 128), 256>>>(py2, W1, b1, nullptr, ph, SQ, FF, DM);

    // FFN2 + residual (C==R aliasing safe: each element read once by its writer)
    hmma_gemm<1><<<gDD, 256>>>(ph, W2, b2, out, out, SQ, DM, FF);
}

// round 4
// speedup vs baseline: 2.6313x; 1.8816x over previous
#include <cuda_runtime.h>
#include <cuda_bf16.h>
#include <math.h>
#include <stdint.h>

#define SQ 4096
#define DM 1024
#define NH 16
#define DHD 64
#define FF 4096

// Scratch (device globals — no runtime allocation allowed)
__device__ float g_y  [SQ*DM];   // LN1 output
__device__ float g_ctx[SQ*DM];
__device__ float g_y2 [SQ*DM];   // LN2 output
__device__ float g_h  [SQ*FF];   // GELU(ffn1) output
__device__ __nv_bfloat16 g_qh[SQ*DM], g_ql[SQ*DM];
__device__ __nv_bfloat16 g_kh[SQ*DM], g_kl[SQ*DM];
__device__ __nv_bfloat16 g_vh[SQ*DM], g_vl[SQ*DM];

// ===========================================================================
// Helpers
// ===========================================================================
__device__ __forceinline__ uint32_t smem_u32(const void* p) {
    uint32_t a;
    asm("{ .reg .u64 t; cvta.to.shared.u64 t, %1; cvt.u32.u64 %0, t; }" : "=r"(a) : "l"(p));
    return a;
}

__device__ __forceinline__ void ldsm4(uint32_t* r, uint32_t addr) {
    asm volatile("ldmatrix.sync.aligned.m8n8.x4.shared.b16 {%0,%1,%2,%3}, [%4];"
        : "=r"(r[0]), "=r"(r[1]), "=r"(r[2]), "=r"(r[3]) : "r"(addr));
}
__device__ __forceinline__ void ldsm4t(uint32_t* r, uint32_t addr) {
    asm volatile("ldmatrix.sync.aligned.m8n8.x4.trans.shared.b16 {%0,%1,%2,%3}, [%4];"
        : "=r"(r[0]), "=r"(r[1]), "=r"(r[2]), "=r"(r[3]) : "r"(addr));
}

__device__ __forceinline__ void mma16816(float* c, const uint32_t* a,
                                         uint32_t b0, uint32_t b1) {
    asm volatile("mma.sync.aligned.m16n8k16.row.col.f32.bf16.bf16.f32 "
        "{%0,%1,%2,%3}, {%4,%5,%6,%7}, {%8,%9}, {%0,%1,%2,%3};"
        : "+f"(c[0]), "+f"(c[1]), "+f"(c[2]), "+f"(c[3])
        : "r"(a[0]), "r"(a[1]), "r"(a[2]), "r"(a[3]), "r"(b0), "r"(b1));
}

__device__ __forceinline__ void split_pack(float x0, float x1, uint32_t& hp, uint32_t& lp) {
    __nv_bfloat16 h0 = __float2bfloat16_rn(x0);
    __nv_bfloat16 h1 = __float2bfloat16_rn(x1);
    __nv_bfloat16 l0 = __float2bfloat16_rn(x0 - __bfloat162float(h0));
    __nv_bfloat16 l1 = __float2bfloat16_rn(x1 - __bfloat162float(h1));
    hp = (uint32_t)__bfloat16_as_ushort(h0) | ((uint32_t)__bfloat16_as_ushort(h1) << 16);
    lp = (uint32_t)__bfloat16_as_ushort(l0) | ((uint32_t)__bfloat16_as_ushort(l1) << 16);
}

__device__ __forceinline__ uint32_t pack_bf16(float x0, float x1) {
    __nv_bfloat162 p = __floats2bfloat162_rn(x0, x1);
    return *(uint32_t*)&p;
}

// ---------------------------------------------------------------------------
// LayerNorm: one block per row, 256 threads, D=1024 (4 elems/thread)
// ---------------------------------------------------------------------------
__global__ __launch_bounds__(256) void ln_kernel(const float* __restrict__ x,
                                                 const float* __restrict__ sc,
                                                 const float* __restrict__ bi,
                                                 float* __restrict__ y)
{
    int row = blockIdx.x;
    const float* xr = x + (size_t)row * DM;
    int t = threadIdx.x;

    float v[4];
    float s = 0.f;
#pragma unroll
    for (int i = 0; i < 4; i++) { v[i] = xr[t + i * 256]; s += v[i]; }

    __shared__ float red[8];
#pragma unroll
    for (int o = 16; o > 0; o >>= 1) s += __shfl_xor_sync(0xffffffffu, s, o);
    if ((t & 31) == 0) red[t >> 5] = s;
    __syncthreads();
    if (t < 32) {
        float r = (t < 8) ? red[t] : 0.f;
#pragma unroll
        for (int o = 4; o > 0; o >>= 1) r += __shfl_xor_sync(0xffffffffu, r, o);
        if (t == 0) red[0] = r;
    }
    __syncthreads();
    float mu = red[0] * (1.0f / DM);
    __syncthreads();

    float vs = 0.f;
#pragma unroll
    for (int i = 0; i < 4; i++) { float d = v[i] - mu; vs += d * d; }
#pragma unroll
    for (int o = 16; o > 0; o >>= 1) vs += __shfl_xor_sync(0xffffffffu, vs, o);
    if ((t & 31) == 0) red[t >> 5] = vs;
    __syncthreads();
    if (t < 32) {
        float r = (t < 8) ? red[t] : 0.f;
#pragma unroll
        for (int o = 4; o > 0; o >>= 1) r += __shfl_xor_sync(0xffffffffu, r, o);
        if (t == 0) red[0] = r;
    }
    __syncthreads();
    float var = red[0] * (1.0f / DM);
    float rstd = rsqrtf(var + 1e-6f);

    float* yr = y + (size_t)row * DM;
#pragma unroll
    for (int i = 0; i < 4; i++) {
        int c = t + i * 256;
        yr[c] = (v[i] - mu) * rstd * sc[c] + bi[c];
    }
}

// ---------------------------------------------------------------------------
// HMMA bf16-split GEMM: Block tile 128x64, BK=32, 8 warps, warp tile 32x32.
// EPI: 0=bias->fp32; 1=bias+residual->fp32; 2=bias+GELU->fp32;
//      3=(bias)*oscale -> hi/lo bf16 split arrays (Hh/Hl), no fp32 out.
// ---------------------------------------------------------------------------
#define ASTRIDE 40   // halfwords; 80 bytes
template <int EPI>
__global__ __launch_bounds__(256, 2) void hmma_gemm(const float* __restrict__ A,
                                                    const float* __restrict__ B,
                                                    const float* __restrict__ bias,
                                                    const float* __restrict__ R,
                                                    float* __restrict__ C,
                                                    __nv_bfloat16* __restrict__ Hh,
                                                    __nv_bfloat16* __restrict__ Hl,
                                                    float oscale,
                                                    int M, int N, int K)
{
    __shared__ __align__(16) __nv_bfloat16 sAh[128 * ASTRIDE];
    __shared__ __align__(16) __nv_bfloat16 sAl[128 * ASTRIDE];
    __shared__ __align__(16) __nv_bfloat16 sBh[64 * ASTRIDE];
    __shared__ __align__(16) __nv_bfloat16 sBl[64 * ASTRIDE];

    const int t = threadIdx.x;
    const int lane = t & 31, w = t >> 5;
    const int wm = w & 3, wn = w >> 2;
    const int row0 = blockIdx.y * 128, col0 = blockIdx.x * 64;

    const uint32_t uAh = smem_u32(sAh), uAl = smem_u32(sAl);
    const uint32_t uBh = smem_u32(sBh), uBl = smem_u32(sBl);

    uint32_t aOff[2];
#pragma unroll
    for (int i = 0; i < 2; i++) {
        int r = wm * 32 + i * 16 + (lane & 7) + 8 * ((lane >> 3) & 1);
        aOff[i] = (uint32_t)(r * (ASTRIDE * 2) + 16 * (lane >> 4));
    }
    uint32_t bOff[2];
#pragma unroll
    for (int jj = 0; jj < 2; jj++) {
        int n = wn * 32 + jj * 16 + (lane & 7) + 8 * (lane >> 4);
        bOff[jj] = (uint32_t)(n * (ASTRIDE * 2) + 16 * ((lane >> 3) & 1));
    }

    float acc[2][4][4] = {};

    const int a_k2 = t & 15;
    const int a_m0 = t >> 4;
    const int b_n  = t & 63;
    const int b_g  = t >> 6;

    for (int k0 = 0; k0 < K; k0 += 32) {
#pragma unroll
        for (int it = 0; it < 8; it++) {
            int m = a_m0 + 16 * it;
            float2 a = *(const float2*)(A + (size_t)(row0 + m) * K + k0 + 2 * a_k2);
            uint32_t hp, lp;
            split_pack(a.x, a.y, hp, lp);
            uint32_t off = (uint32_t)(m * (ASTRIDE * 2) + a_k2 * 4);
            *(uint32_t*)((char*)sAh + off) = hp;
            *(uint32_t*)((char*)sAl + off) = lp;
        }
#pragma unroll
        for (int it = 0; it < 4; it++) {
            int kp = b_g + 4 * it;
            float b0 = B[(size_t)(k0 + 2 * kp)     * N + col0 + b_n];
            float b1 = B[(size_t)(k0 + 2 * kp + 1) * N + col0 + b_n];
            uint32_t hp, lp;
            split_pack(b0, b1, hp, lp);
            uint32_t off = (uint32_t)(b_n * (ASTRIDE * 2) + kp * 4);
            *(uint32_t*)((char*)sBh + off) = hp;
            *(uint32_t*)((char*)sBl + off) = lp;
        }
        __syncthreads();

#pragma unroll
        for (int ks = 0; ks < 2; ks++) {
            const uint32_t kb = ks * 32;
            uint32_t ah[2][4], al[2][4], bh[2][4], bl[2][4];
#pragma unroll
            for (int i = 0; i < 2; i++) {
                ldsm4(ah[i], uAh + aOff[i] + kb);
                ldsm4(al[i], uAl + aOff[i] + kb);
            }
#pragma unroll
            for (int jj = 0; jj < 2; jj++) {
                ldsm4(bh[jj], uBh + bOff[jj] + kb);
                ldsm4(bl[jj], uBl + bOff[jj] + kb);
            }
#pragma unroll
            for (int i = 0; i < 2; i++)
#pragma unroll
                for (int j = 0; j < 4; j++) {
                    const int jj = j >> 1, e = (j & 1) * 2;
                    mma16816(acc[i][j], ah[i], bh[jj][e], bh[jj][e + 1]);
                    mma16816(acc[i][j], ah[i], bl[jj][e], bl[jj][e + 1]);
                    mma16816(acc[i][j], al[i], bh[jj][e], bh[jj][e + 1]);
                }
        }
        __syncthreads();
    }

    // --- epilogue ---
#pragma unroll
    for (int i = 0; i < 2; i++) {
#pragma unroll
        for (int j = 0; j < 4; j++) {
            int r = row0 + wm * 32 + i * 16 + (lane >> 2);
            int c = col0 + wn * 32 + j * 8 + 2 * (lane & 3);
#pragma unroll
            for (int half = 0; half < 2; half++) {
                int rr = r + half * 8;
                float2 v;
                v.x = acc[i][j][half * 2 + 0] + bias[c];
                v.y = acc[i][j][half * 2 + 1] + bias[c + 1];
                size_t idx = (size_t)rr * N + c;
                if (EPI == 3) {
                    v.x *= oscale; v.y *= oscale;
                    uint32_t hp, lp;
                    split_pack(v.x, v.y, hp, lp);
                    *(uint32_t*)(Hh + idx) = hp;
                    *(uint32_t*)(Hl + idx) = lp;
                } else {
                    if (EPI == 1) {
                        float2 r2 = *(const float2*)(R + idx);
                        v.x += r2.x; v.y += r2.y;
                    }
                    if (EPI == 2) {
                        v.x = 0.5f * v.x * (1.0f + erff(v.x * 0.70710678118654752f));
                        v.y = 0.5f * v.y * (1.0f + erff(v.y * 0.70710678118654752f));
                    }
                    *(float2*)(C + idx) = v;
                }
            }
        }
    }
}

// ---------------------------------------------------------------------------
// HMMA flash attention. Block = 128 q-rows x 1 head, 8 warps x 16 q-rows.
// kv tile 64. Q/K split hi/lo (3-term S); P plain bf16, V split (2-term PV).
// smem rows: 64 halfs data + 8 pad = 72 halfs = 144B stride (ldsm-conflict-free).
// ---------------------------------------------------------------------------
#define TSTR 72                      // halfwords per smem row
#define TSTRB (TSTR * 2)             // 144 bytes
#define AQH 0u
#define AQL (128u * TSTRB)           // 18432
#define AKH (2u * 128u * TSTRB)      // 36864
#define AKL (AKH + 64u * TSTRB)
#define AVH (AKH + 2u * 64u * TSTRB)
#define AVL (AKH + 3u * 64u * TSTRB)
#define ATTN_SMEM (2u * 128u * TSTRB + 4u * 64u * TSTRB)   // 73728

__global__ __launch_bounds__(256, 2) void attn_bf16(
    const __nv_bfloat16* __restrict__ qh, const __nv_bfloat16* __restrict__ ql,
    const __nv_bfloat16* __restrict__ kh, const __nv_bfloat16* __restrict__ kl,
    const __nv_bfloat16* __restrict__ vh, const __nv_bfloat16* __restrict__ vl,
    float* __restrict__ ctx)
{
    extern __shared__ char smem[];
    const uint32_t sb = smem_u32(smem);
    const int t = threadIdx.x;
    const int lane = t & 31, w = t >> 5;
    const int h = blockIdx.y;
    const int q0 = blockIdx.x * 128;
    const size_t hoff = (size_t)h * DHD;

    // ---- load Q tile (128 x 64 bf16 hi/lo) ----
#pragma unroll
    for (int it = 0; it < 4; it++) {
        int idx = t + 256 * it;
        int r = idx >> 3, c = idx & 7;
        size_t g = (size_t)(q0 + r) * DM + hoff + c * 8;
        uint32_t so = (uint32_t)(r * TSTRB + c * 16);
        *(uint4*)(smem + AQH + so) = *(const uint4*)(qh + g);
        *(uint4*)(smem + AQL + so) = *(const uint4*)(ql + g);
    }

    // ldsm offset patterns
    const uint32_t aOff = (uint32_t)((w * 16 + (lane & 15)) * TSTRB + 16 * (lane >> 4));
    uint32_t bOff[4];
#pragma unroll
    for (int ng = 0; ng < 4; ng++)
        bOff[ng] = (uint32_t)((ng * 16 + (lane & 7) + 8 * (lane >> 4)) * TSTRB
                              + 16 * ((lane >> 3) & 1));
    const uint32_t vOff = (uint32_t)(((lane & 7) + 8 * ((lane >> 3) & 1)) * TSTRB
                                     + 16 * (lane >> 4));

    float of[8][4] = {};
    float m0 = -1e30f, m1 = -1e30f, l0 = 0.f, l1 = 0.f;
    __syncthreads();

    for (int kb = 0; kb < SQ / 64; kb++) {
        const int k0 = kb * 64;

        // ---- load K/V tiles (64 x 64 bf16, 4 arrays) ----
#pragma unroll
        for (int it = 0; it < 2; it++) {
            int idx = t + 256 * it;
            int r = idx >> 3, c = idx & 7;
            size_t g = (size_t)(k0 + r) * DM + hoff + c * 8;
            uint32_t so = (uint32_t)(r * TSTRB + c * 16);
            *(uint4*)(smem + AKH + so) = *(const uint4*)(kh + g);
            *(uint4*)(smem + AKL + so) = *(const uint4*)(kl + g);
            *(uint4*)(smem + AVH + so) = *(const uint4*)(vh + g);
            *(uint4*)(smem + AVL + so) = *(const uint4*)(vl + g);
        }
        __syncthreads();

        // ---- S = Q @ K^T  (m16 x n64, 3-term split) ----
        float sa[8][4] = {};
#pragma unroll
        for (int ks = 0; ks < 4; ks++) {
            const uint32_t kbyte = ks * 32;
            uint32_t qfh[4], qfl[4];
            ldsm4(qfh, sb + AQH + aOff + kbyte);
            ldsm4(qfl, sb + AQL + aOff + kbyte);
#pragma unroll
            for (int ng = 0; ng < 4; ng++) {
                uint32_t kfh[4], kfl[4];
                ldsm4(kfh, sb + AKH + bOff[ng] + kbyte);
                ldsm4(kfl, sb + AKL + bOff[ng] + kbyte);
                mma16816(sa[2 * ng],     qfh, kfh[0], kfh[1]);
                mma16816(sa[2 * ng + 1], qfh, kfh[2], kfh[3]);
                mma16816(sa[2 * ng],     qfh, kfl[0], kfl[1]);
                mma16816(sa[2 * ng + 1], qfh, kfl[2], kfl[3]);
                mma16816(sa[2 * ng],     qfl, kfh[0], kfh[1]);
                mma16816(sa[2 * ng + 1], qfl, kfh[2], kfh[3]);
            }
        }

        // ---- online softmax (rows r=lane>>2 and r+8; quad shfl reduce) ----
        float mx0 = -1e30f, mx1 = -1e30f;
#pragma unroll
        for (int nf = 0; nf < 8; nf++) {
            mx0 = fmaxf(mx0, fmaxf(sa[nf][0], sa[nf][1]));
            mx1 = fmaxf(mx1, fmaxf(sa[nf][2], sa[nf][3]));
        }
#pragma unroll
        for (int o = 1; o <= 2; o <<= 1) {
            mx0 = fmaxf(mx0, __shfl_xor_sync(0xffffffffu, mx0, o));
            mx1 = fmaxf(mx1, __shfl_xor_sync(0xffffffffu, mx1, o));
        }
        float mn0 = fmaxf(m0, mx0), mn1 = fmaxf(m1, mx1);
        float al0 = __expf(m0 - mn0), al1 = __expf(m1 - mn1);
        m0 = mn0; m1 = mn1;
        float rs0 = 0.f, rs1 = 0.f;
#pragma unroll
        for (int nf = 0; nf < 8; nf++) {
            sa[nf][0] = __expf(sa[nf][0] - mn0);
            sa[nf][1] = __expf(sa[nf][1] - mn0);
            sa[nf][2] = __expf(sa[nf][2] - mn1);
            sa[nf][3] = __expf(sa[nf][3] - mn1);
            rs0 += sa[nf][0] + sa[nf][1];
            rs1 += sa[nf][2] + sa[nf][3];
        }
#pragma unroll
        for (int o = 1; o <= 2; o <<= 1) {
            rs0 += __shfl_xor_sync(0xffffffffu, rs0, o);
            rs1 += __shfl_xor_sync(0xffffffffu, rs1, o);
        }
        l0 = l0 * al0 + rs0;
        l1 = l1 * al1 + rs1;
#pragma unroll
        for (int nf = 0; nf < 8; nf++) {
            of[nf][0] *= al0; of[nf][1] *= al0;
            of[nf][2] *= al1; of[nf][3] *= al1;
        }

        // ---- O += P @ V  (P from S-frags, V via ldmatrix.trans, 2-term) ----
#pragma unroll
        for (int j = 0; j < 4; j++) {          // kv16 steps
            uint32_t pa[4];
            pa[0] = pack_bf16(sa[2 * j][0],     sa[2 * j][1]);
            pa[1] = pack_bf16(sa[2 * j][2],     sa[2 * j][3]);
            pa[2] = pack_bf16(sa[2 * j + 1][0], sa[2 * j + 1][1]);
            pa[3] = pack_bf16(sa[2 * j + 1][2], sa[2 * j + 1][3]);
            const uint32_t tOff = vOff + (uint32_t)(j * 16 * TSTRB);
#pragma unroll
            for (int g = 0; g < 4; g++) {      // d16 groups
                uint32_t vfh[4], vfl[4];
                ldsm4t(vfh, sb + AVH + tOff + g * 32);
                ldsm4t(vfl, sb + AVL + tOff + g * 32);
                mma16816(of[2 * g],     pa, vfh[0], vfh[1]);
                mma16816(of[2 * g + 1], pa, vfh[2], vfh[3]);
                mma16816(of[2 * g],     pa, vfl[0], vfl[1]);
                mma16816(of[2 * g + 1], pa, vfl[2], vfl[3]);
            }
        }
        __syncthreads();
    }

    // ---- epilogue: normalize, write ctx (fp32) ----
    const float inv0 = 1.0f / l0, inv1 = 1.0f / l1;
    const int r0 = q0 + w * 16 + (lane >> 2);
#pragma unroll
    for (int nf = 0; nf < 8; nf++) {
        int d = nf * 8 + 2 * (lane & 3);
        float2 v0 = make_float2(of[nf][0] * inv0, of[nf][1] * inv0);
        float2 v1 = make_float2(of[nf][2] * inv1, of[nf][3] * inv1);
        *(float2*)(ctx + (size_t)r0 * DM + hoff + d) = v0;
        *(float2*)(ctx + (size_t)(r0 + 8) * DM + hoff + d) = v1;
    }
}

// ---------------------------------------------------------------------------
extern "C" void kernel_launch(void* const* d_in, const int* in_sizes, int n_in,
                              void* d_out, int out_size)
{
    const float* x   = (const float*)d_in[0];
    const float* Wq  = (const float*)d_in[1];
    const float* bq  = (const float*)d_in[2];
    const float* Wk  = (const float*)d_in[3];
    const float* bk  = (const float*)d_in[4];
    const float* Wv  = (const float*)d_in[5];
    const float* bv  = (const float*)d_in[6];
    const float* Wo  = (const float*)d_in[7];
    const float* bo  = (const float*)d_in[8];
    const float* l1s = (const float*)d_in[9];
    const float* l1b = (const float*)d_in[10];
    const float* l2s = (const float*)d_in[11];
    const float* l2b = (const float*)d_in[12];
    const float* W1  = (const float*)d_in[13];
    const float* b1  = (const float*)d_in[14];
    const float* W2  = (const float*)d_in[15];
    const float* b2  = (const float*)d_in[16];
    float* out = (float*)d_out;

    float *py, *pctx, *py2, *ph;
    __nv_bfloat16 *pqh, *pql, *pkh, *pkl, *pvh, *pvl;
    cudaGetSymbolAddress((void**)&py,   g_y);
    cudaGetSymbolAddress((void**)&pctx, g_ctx);
    cudaGetSymbolAddress((void**)&py2,  g_y2);
    cudaGetSymbolAddress((void**)&ph,   g_h);
    cudaGetSymbolAddress((void**)&pqh,  g_qh);
    cudaGetSymbolAddress((void**)&pql,  g_ql);
    cudaGetSymbolAddress((void**)&pkh,  g_kh);
    cudaGetSymbolAddress((void**)&pkl,  g_kl);
    cudaGetSymbolAddress((void**)&pvh,  g_vh);
    cudaGetSymbolAddress((void**)&pvl,  g_vl);

    cudaFuncSetAttribute(attn_bf16, cudaFuncAttributeMaxDynamicSharedMemorySize,
                         ATTN_SMEM);

    // LN1
    ln_kernel<<<SQ, 256>>>(x, l1s, l1b, py);

    // QKV projections -> split bf16 (Q pre-scaled by 1/sqrt(DH))
    dim3 gDD(DM / 64, SQ / 128);
    hmma_gemm<3><<<gDD, 256>>>(py, Wq, bq, nullptr, nullptr, pqh, pql, 0.125f, SQ, DM, DM);
    hmma_gemm<3><<<gDD, 256>>>(py, Wk, bk, nullptr, nullptr, pkh, pkl, 1.0f,   SQ, DM, DM);
    hmma_gemm<3><<<gDD, 256>>>(py, Wv, bv, nullptr, nullptr, pvh, pvl, 1.0f,   SQ, DM, DM);

    // Attention (HMMA flash)
    attn_bf16<<<dim3(SQ / 128, NH), 256, ATTN_SMEM>>>(pqh, pql, pkh, pkl, pvh, pvl, pctx);

    // Output projection + residual
    hmma_gemm<1><<<gDD, 256>>>(pctx, Wo, bo, x, out, nullptr, nullptr, 1.0f, SQ, DM, DM);

    // LN2
    ln_kernel<<<SQ, 256>>>(out, l2s, l2b, py2);

    // FFN1 + GELU
    hmma_gemm<2><<<dim3(FF / 64, SQ / 128), 256>>>(py2, W1, b1, nullptr, ph, nullptr, nullptr, 1.0f, SQ, FF, DM);

    // FFN2 + residual (C==R aliasing safe: each element read once by its writer)
    hmma_gemm<1><<<gDD, 256>>>(ph, W2, b2, out, out, nullptr, nullptr, 1.0f, SQ, DM, FF);
}

// round 5
// speedup vs baseline: 3.1359x; 1.1918x over previous
#include <cuda_runtime.h>
#include <cuda_bf16.h>
#include <math.h>
#include <stdint.h>

#define SQ 4096
#define DM 1024
#define NH 16
#define DHD 64
#define FF 4096
#define QKVN 3072

typedef __nv_bfloat16 bf16;

// Scratch (device globals — no runtime allocation allowed)
__device__ bf16 g_yh [SQ*DM],   g_yl [SQ*DM];    // LN1 out split
__device__ bf16 g_qkvh[SQ*QKVN],g_qkvl[SQ*QKVN]; // packed q|k|v split
__device__ bf16 g_ctxh[SQ*DM],  g_ctxl[SQ*DM];   // attention out split
__device__ bf16 g_y2h[SQ*DM],   g_y2l[SQ*DM];    // LN2 out split
__device__ bf16 g_hh [SQ*FF],   g_hl [SQ*FF];    // GELU out split
// transposed split weights [N][K]
__device__ bf16 g_wqkvh[QKVN*DM], g_wqkvl[QKVN*DM];
__device__ bf16 g_woh [DM*DM],  g_wol [DM*DM];
__device__ bf16 g_w1h [FF*DM],  g_w1l [FF*DM];
__device__ bf16 g_w2h [DM*FF],  g_w2l [DM*FF];
__device__ float g_bqkv[QKVN];

// ===========================================================================
// Helpers
// ===========================================================================
__device__ __forceinline__ uint32_t smem_u32(const void* p) {
    uint32_t a;
    asm("{ .reg .u64 t; cvta.to.shared.u64 t, %1; cvt.u32.u64 %0, t; }" : "=r"(a) : "l"(p));
    return a;
}
__device__ __forceinline__ void ldsm4(uint32_t* r, uint32_t addr) {
    asm volatile("ldmatrix.sync.aligned.m8n8.x4.shared.b16 {%0,%1,%2,%3}, [%4];"
        : "=r"(r[0]), "=r"(r[1]), "=r"(r[2]), "=r"(r[3]) : "r"(addr));
}
__device__ __forceinline__ void ldsm4t(uint32_t* r, uint32_t addr) {
    asm volatile("ldmatrix.sync.aligned.m8n8.x4.trans.shared.b16 {%0,%1,%2,%3}, [%4];"
        : "=r"(r[0]), "=r"(r[1]), "=r"(r[2]), "=r"(r[3]) : "r"(addr));
}
__device__ __forceinline__ void mma16816(float* c, const uint32_t* a,
                                         uint32_t b0, uint32_t b1) {
    asm volatile("mma.sync.aligned.m16n8k16.row.col.f32.bf16.bf16.f32 "
        "{%0,%1,%2,%3}, {%4,%5,%6,%7}, {%8,%9}, {%0,%1,%2,%3};"
        : "+f"(c[0]), "+f"(c[1]), "+f"(c[2]), "+f"(c[3])
        : "r"(a[0]), "r"(a[1]), "r"(a[2]), "r"(a[3]), "r"(b0), "r"(b1));
}
__device__ __forceinline__ void cpasync16(uint32_t dst, const void* src) {
    asm volatile("cp.async.cg.shared.global [%0], [%1], 16;" :: "r"(dst), "l"(src));
}
#define CP_COMMIT() asm volatile("cp.async.commit_group;" ::: "memory")
#define CP_WAIT(n)  asm volatile("cp.async.wait_group %0;" :: "n"(n) : "memory")

__device__ __forceinline__ void split_pack(float x0, float x1, uint32_t& hp, uint32_t& lp) {
    bf16 h0 = __float2bfloat16_rn(x0);
    bf16 h1 = __float2bfloat16_rn(x1);
    bf16 l0 = __float2bfloat16_rn(x0 - __bfloat162float(h0));
    bf16 l1 = __float2bfloat16_rn(x1 - __bfloat162float(h1));
    hp = (uint32_t)__bfloat16_as_ushort(h0) | ((uint32_t)__bfloat16_as_ushort(h1) << 16);
    lp = (uint32_t)__bfloat16_as_ushort(l0) | ((uint32_t)__bfloat16_as_ushort(l1) << 16);
}
__device__ __forceinline__ uint32_t pack_bf16(float x0, float x1) {
    __nv_bfloat162 p = __floats2bfloat162_rn(x0, x1);
    return *(uint32_t*)&p;
}

// ---------------------------------------------------------------------------
// Weight transpose + split: W[K][N] fp32 -> Th/Tl[N][K] bf16
// ---------------------------------------------------------------------------
__global__ __launch_bounds__(256) void wconv(const float* __restrict__ W,
                                             bf16* __restrict__ Th,
                                             bf16* __restrict__ Tl,
                                             int K, int N)
{
    __shared__ float tile[32][33];
    const int n0 = blockIdx.x * 32, k0 = blockIdx.y * 32;
    const int t = threadIdx.x;
#pragma unroll
    for (int i = 0; i < 4; i++) {
        int idx = t + 256 * i;
        int kr = idx >> 5, nc = idx & 31;
        tile[kr][nc] = W[(size_t)(k0 + kr) * N + n0 + nc];
    }
    __syncthreads();
#pragma unroll
    for (int i = 0; i < 2; i++) {
        int idx = t + 256 * i;
        int n = idx >> 4, c = idx & 15;
        uint32_t hp, lp;
        split_pack(tile[2 * c][n], tile[2 * c + 1][n], hp, lp);
        size_t o = (size_t)(n0 + n) * K + k0 + 2 * c;
        *(uint32_t*)(Th + o) = hp;
        *(uint32_t*)(Tl + o) = lp;
    }
}

__global__ void pack_bias(const float* __restrict__ bq, const float* __restrict__ bk,
                          const float* __restrict__ bv, float* __restrict__ dst)
{
    int i = blockIdx.x * 256 + threadIdx.x;
    if (i < 1024) dst[i] = bq[i];
    else if (i < 2048) dst[i] = bk[i - 1024];
    else if (i < QKVN) dst[i] = bv[i - 2048];
}

// ---------------------------------------------------------------------------
// LayerNorm -> split bf16. One block/row, 256 threads, 4 consecutive elems/thread.
// ---------------------------------------------------------------------------
__global__ __launch_bounds__(256) void ln_split(const float* __restrict__ x,
                                                const float* __restrict__ sc,
                                                const float* __restrict__ bi,
                                                bf16* __restrict__ yh,
                                                bf16* __restrict__ yl)
{
    int row = blockIdx.x;
    const float* xr = x + (size_t)row * DM;
    int t = threadIdx.x;

    float4 v = *(const float4*)(xr + 4 * t);
    float s = v.x + v.y + v.z + v.w;

    __shared__ float red[8];
#pragma unroll
    for (int o = 16; o > 0; o >>= 1) s += __shfl_xor_sync(0xffffffffu, s, o);
    if ((t & 31) == 0) red[t >> 5] = s;
    __syncthreads();
    if (t < 32) {
        float r = (t < 8) ? red[t] : 0.f;
#pragma unroll
        for (int o = 4; o > 0; o >>= 1) r += __shfl_xor_sync(0xffffffffu, r, o);
        if (t == 0) red[0] = r;
    }
    __syncthreads();
    float mu = red[0] * (1.0f / DM);
    __syncthreads();

    float d0 = v.x - mu, d1 = v.y - mu, d2 = v.z - mu, d3 = v.w - mu;
    float vs = d0 * d0 + d1 * d1 + d2 * d2 + d3 * d3;
#pragma unroll
    for (int o = 16; o > 0; o >>= 1) vs += __shfl_xor_sync(0xffffffffu, vs, o);
    if ((t & 31) == 0) red[t >> 5] = vs;
    __syncthreads();
    if (t < 32) {
        float r = (t < 8) ? red[t] : 0.f;
#pragma unroll
        for (int o = 4; o > 0; o >>= 1) r += __shfl_xor_sync(0xffffffffu, r, o);
        if (t == 0) red[0] = r;
    }
    __syncthreads();
    float rstd = rsqrtf(red[0] * (1.0f / DM) + 1e-6f);

    float4 s4 = *(const float4*)(sc + 4 * t);
    float4 b4 = *(const float4*)(bi + 4 * t);
    float n0 = d0 * rstd * s4.x + b4.x;
    float n1 = d1 * rstd * s4.y + b4.y;
    float n2 = d2 * rstd * s4.z + b4.z;
    float n3 = d3 * rstd * s4.w + b4.w;
    uint32_t h0, l0, h1, l1;
    split_pack(n0, n1, h0, l0);
    split_pack(n2, n3, h1, l1);
    size_t o = (size_t)row * DM + 4 * t;
    *(uint2*)(yh + o) = make_uint2(h0, h1);
    *(uint2*)(yl + o) = make_uint2(l0, l1);
}

// ---------------------------------------------------------------------------
// Pure-bf16 HMMA split GEMM, cp.async double-buffered.
// A[M][K] split (Ah/Al), B[N][K] split (Bh/Bl). Tile 128x64, BK=32, 8 warps.
// EPI: 1 = +bias+residual -> fp32 C
//      2 = +bias, GELU -> split bf16 (Oh/Ol, ostride)
//      3 = +bias, x0.125 on cols<1024 -> split bf16 (QKV packed, ostride)
// ---------------------------------------------------------------------------
#define OFF_AH 0u
#define OFF_AL 10240u
#define OFF_BH 20480u
#define OFF_BL 25600u
#define STAGE  30720u
#define GSMEM  (2u * STAGE)

template <int EPI>
__global__ __launch_bounds__(256, 2) void gemm_bf16(
    const bf16* __restrict__ Ah, const bf16* __restrict__ Al,
    const bf16* __restrict__ Bh, const bf16* __restrict__ Bl,
    const float* __restrict__ bias, const float* __restrict__ R,
    float* __restrict__ C, bf16* __restrict__ Oh, bf16* __restrict__ Ol,
    int ostride, int N, int K)
{
    extern __shared__ char smem[];
    const uint32_t sb = smem_u32(smem);
    const int t = threadIdx.x;
    const int lane = t & 31, w = t >> 5;
    const int wm = w & 3, wn = w >> 2;
    const int row0 = blockIdx.y * 128, col0 = blockIdx.x * 64;

    // ldsm lane offsets (within array region; stride 80B/row)
    uint32_t aOff[2];
#pragma unroll
    for (int i = 0; i < 2; i++) {
        int r = wm * 32 + i * 16 + (lane & 7) + 8 * ((lane >> 3) & 1);
        aOff[i] = (uint32_t)(r * 80 + 16 * (lane >> 4));
    }
    uint32_t bOff[2];
#pragma unroll
    for (int jj = 0; jj < 2; jj++) {
        int n = wn * 32 + jj * 16 + (lane & 7) + 8 * (lane >> 4);
        bOff[jj] = (uint32_t)(n * 80 + 16 * ((lane >> 3) & 1));
    }

    // cp.async source/dst indices
    const int am = t >> 2, ac = t & 3;          // A: rows t>>2 and +64
    const int bn = t >> 2, bc = t & 3;          // B: row t>>2

    auto load_tile = [&](int kc, int buf) {
        const uint32_t base = sb + buf * STAGE;
        const int k0 = kc * 32;
#pragma unroll
        for (int i = 0; i < 2; i++) {
            int m = am + 64 * i;
            size_t g = (size_t)(row0 + m) * K + k0 + ac * 8;
            uint32_t d = base + (uint32_t)(m * 80 + ac * 16);
            cpasync16(d + OFF_AH, Ah + g);
            cpasync16(d + OFF_AL, Al + g);
        }
        {
            size_t g = (size_t)(col0 + bn) * K + k0 + bc * 8;
            uint32_t d = base + (uint32_t)(bn * 80 + bc * 16);
            cpasync16(d + OFF_BH, Bh + g);
            cpasync16(d + OFF_BL, Bl + g);
        }
    };

    float acc[2][4][4] = {};

    const int nk = K >> 5;
    load_tile(0, 0);
    CP_COMMIT();

    for (int kc = 0; kc < nk; kc++) {
        if (kc + 1 < nk) {
            load_tile(kc + 1, (kc + 1) & 1);
            CP_COMMIT();
            CP_WAIT(1);
        } else {
            CP_WAIT(0);
        }
        __syncthreads();

        const uint32_t bs = sb + (kc & 1) * STAGE;
#pragma unroll
        for (int ks = 0; ks < 2; ks++) {
            const uint32_t kb = ks * 32;
            uint32_t ah[2][4], al[2][4], bh[2][4], bl[2][4];
#pragma unroll
            for (int i = 0; i < 2; i++) {
                ldsm4(ah[i], bs + OFF_AH + aOff[i] + kb);
                ldsm4(al[i], bs + OFF_AL + aOff[i] + kb);
            }
#pragma unroll
            for (int jj = 0; jj < 2; jj++) {
                ldsm4(bh[jj], bs + OFF_BH + bOff[jj] + kb);
                ldsm4(bl[jj], bs + OFF_BL + bOff[jj] + kb);
            }
#pragma unroll
            for (int i = 0; i < 2; i++)
#pragma unroll
                for (int j = 0; j < 4; j++) {
                    const int jj = j >> 1, e = (j & 1) * 2;
                    mma16816(acc[i][j], ah[i], bh[jj][e], bh[jj][e + 1]);
                    mma16816(acc[i][j], ah[i], bl[jj][e], bl[jj][e + 1]);
                    mma16816(acc[i][j], al[i], bh[jj][e], bh[jj][e + 1]);
                }
        }
        __syncthreads();
    }

    // --- epilogue ---
#pragma unroll
    for (int i = 0; i < 2; i++) {
#pragma unroll
        for (int j = 0; j < 4; j++) {
            int r = row0 + wm * 32 + i * 16 + (lane >> 2);
            int cg = col0 + wn * 32 + j * 8 + 2 * (lane & 3);
#pragma unroll
            for (int half = 0; half < 2; half++) {
                int rr = r + half * 8;
                float vx = acc[i][j][half * 2 + 0] + bias[cg];
                float vy = acc[i][j][half * 2 + 1] + bias[cg + 1];
                if (EPI == 1) {
                    size_t idx = (size_t)rr * N + cg;
                    float2 r2 = *(const float2*)(R + idx);
                    *(float2*)(C + idx) = make_float2(vx + r2.x, vy + r2.y);
                } else {
                    if (EPI == 2) {
                        vx = 0.5f * vx * (1.0f + erff(vx * 0.70710678118654752f));
                        vy = 0.5f * vy * (1.0f + erff(vy * 0.70710678118654752f));
                    }
                    if (EPI == 3 && cg < 1024) { vx *= 0.125f; vy *= 0.125f; }
                    uint32_t hp, lp;
                    split_pack(vx, vy, hp, lp);
                    size_t idx = (size_t)rr * ostride + cg;
                    *(uint32_t*)(Oh + idx) = hp;
                    *(uint32_t*)(Ol + idx) = lp;
                }
            }
        }
    }
}

// ---------------------------------------------------------------------------
// HMMA flash attention over packed split-QKV (row stride 3072).
// Block = 128 q-rows x 1 head, 8 warps. kv tile 64.
// ---------------------------------------------------------------------------
#define TSTRB 144
#define AQH 0u
#define AQL (128u * TSTRB)
#define AKH (2u * 128u * TSTRB)
#define AKL (AKH + 64u * TSTRB)
#define AVH (AKH + 2u * 64u * TSTRB)
#define AVL (AKH + 3u * 64u * TSTRB)
#define ATTN_SMEM (2u * 128u * TSTRB + 4u * 64u * TSTRB)

__global__ __launch_bounds__(256, 2) void attn_bf16(
    const bf16* __restrict__ qkvh, const bf16* __restrict__ qkvl,
    bf16* __restrict__ ctxh, bf16* __restrict__ ctxl)
{
    extern __shared__ char smem[];
    const uint32_t sb = smem_u32(smem);
    const int t = threadIdx.x;
    const int lane = t & 31, w = t >> 5;
    const int h = blockIdx.y;
    const int q0 = blockIdx.x * 128;
    const int hcol = h * DHD;

    // ---- load Q tile ----
#pragma unroll
    for (int it = 0; it < 4; it++) {
        int idx = t + 256 * it;
        int r = idx >> 3, c = idx & 7;
        size_t g = (size_t)(q0 + r) * QKVN + hcol + c * 8;
        uint32_t so = (uint32_t)(r * TSTRB + c * 16);
        *(uint4*)(smem + AQH + so) = *(const uint4*)(qkvh + g);
        *(uint4*)(smem + AQL + so) = *(const uint4*)(qkvl + g);
    }

    const uint32_t aOff = (uint32_t)((w * 16 + (lane & 15)) * TSTRB + 16 * (lane >> 4));
    uint32_t bOff[4];
#pragma unroll
    for (int ng = 0; ng < 4; ng++)
        bOff[ng] = (uint32_t)((ng * 16 + (lane & 7) + 8 * (lane >> 4)) * TSTRB
                              + 16 * ((lane >> 3) & 1));
    const uint32_t vOff = (uint32_t)(((lane & 7) + 8 * ((lane >> 3) & 1)) * TSTRB
                                     + 16 * (lane >> 4));

    float of[8][4] = {};
    float m0 = -1e30f, m1 = -1e30f, l0 = 0.f, l1 = 0.f;
    __syncthreads();

    for (int kb = 0; kb < SQ / 64; kb++) {
        const int k0 = kb * 64;

#pragma unroll
        for (int it = 0; it < 2; it++) {
            int idx = t + 256 * it;
            int r = idx >> 3, c = idx & 7;
            size_t gk = (size_t)(k0 + r) * QKVN + 1024 + hcol + c * 8;
            size_t gv = gk + 1024;
            uint32_t so = (uint32_t)(r * TSTRB + c * 16);
            *(uint4*)(smem + AKH + so) = *(const uint4*)(qkvh + gk);
            *(uint4*)(smem + AKL + so) = *(const uint4*)(qkvl + gk);
            *(uint4*)(smem + AVH + so) = *(const uint4*)(qkvh + gv);
            *(uint4*)(smem + AVL + so) = *(const uint4*)(qkvl + gv);
        }
        __syncthreads();

        // ---- S = Q @ K^T (3-term split) ----
        float sa[8][4] = {};
#pragma unroll
        for (int ks = 0; ks < 4; ks++) {
            const uint32_t kbyte = ks * 32;
            uint32_t qfh[4], qfl[4];
            ldsm4(qfh, sb + AQH + aOff + kbyte);
            ldsm4(qfl, sb + AQL + aOff + kbyte);
#pragma unroll
            for (int ng = 0; ng < 4; ng++) {
                uint32_t kfh[4], kfl[4];
                ldsm4(kfh, sb + AKH + bOff[ng] + kbyte);
                ldsm4(kfl, sb + AKL + bOff[ng] + kbyte);
                mma16816(sa[2 * ng],     qfh, kfh[0], kfh[1]);
                mma16816(sa[2 * ng + 1], qfh, kfh[2], kfh[3]);
                mma16816(sa[2 * ng],     qfh, kfl[0], kfl[1]);
                mma16816(sa[2 * ng + 1], qfh, kfl[2], kfl[3]);
                mma16816(sa[2 * ng],     qfl, kfh[0], kfh[1]);
                mma16816(sa[2 * ng + 1], qfl, kfh[2], kfh[3]);
            }
        }

        // ---- online softmax ----
        float mx0 = -1e30f, mx1 = -1e30f;
#pragma unroll
        for (int nf = 0; nf < 8; nf++) {
            mx0 = fmaxf(mx0, fmaxf(sa[nf][0], sa[nf][1]));
            mx1 = fmaxf(mx1, fmaxf(sa[nf][2], sa[nf][3]));
        }
#pragma unroll
        for (int o = 1; o <= 2; o <<= 1) {
            mx0 = fmaxf(mx0, __shfl_xor_sync(0xffffffffu, mx0, o));
            mx1 = fmaxf(mx1, __shfl_xor_sync(0xffffffffu, mx1, o));
        }
        float mn0 = fmaxf(m0, mx0), mn1 = fmaxf(m1, mx1);
        float al0 = __expf(m0 - mn0), al1 = __expf(m1 - mn1);
        m0 = mn0; m1 = mn1;
        float rs0 = 0.f, rs1 = 0.f;
#pragma unroll
        for (int nf = 0; nf < 8; nf++) {
            sa[nf][0] = __expf(sa[nf][0] - mn0);
            sa[nf][1] = __expf(sa[nf][1] - mn0);
            sa[nf][2] = __expf(sa[nf][2] - mn1);
            sa[nf][3] = __expf(sa[nf][3] - mn1);
            rs0 += sa[nf][0] + sa[nf][1];
            rs1 += sa[nf][2] + sa[nf][3];
        }
#pragma unroll
        for (int o = 1; o <= 2; o <<= 1) {
            rs0 += __shfl_xor_sync(0xffffffffu, rs0, o);
            rs1 += __shfl_xor_sync(0xffffffffu, rs1, o);
        }
        l0 = l0 * al0 + rs0;
        l1 = l1 * al1 + rs1;
#pragma unroll
        for (int nf = 0; nf < 8; nf++) {
            of[nf][0] *= al0; of[nf][1] *= al0;
            of[nf][2] *= al1; of[nf][3] *= al1;
        }

        // ---- O += P @ V (2-term) ----
#pragma unroll
        for (int j = 0; j < 4; j++) {
            uint32_t pa[4];
            pa[0] = pack_bf16(sa[2 * j][0],     sa[2 * j][1]);
            pa[1] = pack_bf16(sa[2 * j][2],     sa[2 * j][3]);
            pa[2] = pack_bf16(sa[2 * j + 1][0], sa[2 * j + 1][1]);
            pa[3] = pack_bf16(sa[2 * j + 1][2], sa[2 * j + 1][3]);
            const uint32_t tOff = vOff + (uint32_t)(j * 16 * TSTRB);
#pragma unroll
            for (int g = 0; g < 4; g++) {
                uint32_t vfh[4], vfl[4];
                ldsm4t(vfh, sb + AVH + tOff + g * 32);
                ldsm4t(vfl, sb + AVL + tOff + g * 32);
                mma16816(of[2 * g],     pa, vfh[0], vfh[1]);
                mma16816(of[2 * g + 1], pa, vfh[2], vfh[3]);
                mma16816(of[2 * g],     pa, vfl[0], vfl[1]);
                mma16816(of[2 * g + 1], pa, vfl[2], vfl[3]);
            }
        }
        __syncthreads();
    }

    // ---- epilogue: normalize, write split ctx ----
    const float inv0 = 1.0f / l0, inv1 = 1.0f / l1;
    const int r0 = q0 + w * 16 + (lane >> 2);
#pragma unroll
    for (int nf = 0; nf < 8; nf++) {
        int d = nf * 8 + 2 * (lane & 3);
        uint32_t hp, lp;
        size_t i0 = (size_t)r0 * DM + hcol + d;
        size_t i1 = (size_t)(r0 + 8) * DM + hcol + d;
        split_pack(of[nf][0] * inv0, of[nf][1] * inv0, hp, lp);
        *(uint32_t*)(ctxh + i0) = hp; *(uint32_t*)(ctxl + i0) = lp;
        split_pack(of[nf][2] * inv1, of[nf][3] * inv1, hp, lp);
        *(uint32_t*)(ctxh + i1) = hp; *(uint32_t*)(ctxl + i1) = lp;
    }
}

// ---------------------------------------------------------------------------
extern "C" void kernel_launch(void* const* d_in, const int* in_sizes, int n_in,
                              void* d_out, int out_size)
{
    const float* x   = (const float*)d_in[0];
    const float* Wq  = (const float*)d_in[1];
    const float* bq  = (const float*)d_in[2];
    const float* Wk  = (const float*)d_in[3];
    const float* bk  = (const float*)d_in[4];
    const float* Wv  = (const float*)d_in[5];
    const float* bv  = (const float*)d_in[6];
    const float* Wo  = (const float*)d_in[7];
    const float* bo  = (const float*)d_in[8];
    const float* l1s = (const float*)d_in[9];
    const float* l1b = (const float*)d_in[10];
    const float* l2s = (const float*)d_in[11];
    const float* l2b = (const float*)d_in[12];
    const float* W1  = (const float*)d_in[13];
    const float* b1  = (const float*)d_in[14];
    const float* W2  = (const float*)d_in[15];
    const float* b2  = (const float*)d_in[16];
    float* out = (float*)d_out;

    bf16 *yh, *yl, *qkvh, *qkvl, *ctxh, *ctxl, *y2h, *y2l, *hh, *hl;
    bf16 *wqkvh, *wqkvl, *woh, *wol, *w1h, *w1l, *w2h, *w2l;
    float *bqkv;
    cudaGetSymbolAddress((void**)&yh, g_yh);     cudaGetSymbolAddress((void**)&yl, g_yl);
    cudaGetSymbolAddress((void**)&qkvh, g_qkvh); cudaGetSymbolAddress((void**)&qkvl, g_qkvl);
    cudaGetSymbolAddress((void**)&ctxh, g_ctxh); cudaGetSymbolAddress((void**)&ctxl, g_ctxl);
    cudaGetSymbolAddress((void**)&y2h, g_y2h);   cudaGetSymbolAddress((void**)&y2l, g_y2l);
    cudaGetSymbolAddress((void**)&hh, g_hh);     cudaGetSymbolAddress((void**)&hl, g_hl);
    cudaGetSymbolAddress((void**)&wqkvh, g_wqkvh); cudaGetSymbolAddress((void**)&wqkvl, g_wqkvl);
    cudaGetSymbolAddress((void**)&woh, g_woh);   cudaGetSymbolAddress((void**)&wol, g_wol);
    cudaGetSymbolAddress((void**)&w1h, g_w1h);   cudaGetSymbolAddress((void**)&w1l, g_w1l);
    cudaGetSymbolAddress((void**)&w2h, g_w2h);   cudaGetSymbolAddress((void**)&w2l, g_w2l);
    cudaGetSymbolAddress((void**)&bqkv, g_bqkv);

    cudaFuncSetAttribute(attn_bf16, cudaFuncAttributeMaxDynamicSharedMemorySize, ATTN_SMEM);
    cudaFuncSetAttribute(gemm_bf16<1>, cudaFuncAttributeMaxDynamicSharedMemorySize, GSMEM);
    cudaFuncSetAttribute(gemm_bf16<2>, cudaFuncAttributeMaxDynamicSharedMemorySize, GSMEM);
    cudaFuncSetAttribute(gemm_bf16<3>, cudaFuncAttributeMaxDynamicSharedMemorySize, GSMEM);

    // ---- weight prep (once per launch) ----
    pack_bias<<<12, 256>>>(bq, bk, bv, bqkv);
    wconv<<<dim3(32, 32), 256>>>(Wq, wqkvh,                wqkvl,                DM, DM);
    wconv<<<dim3(32, 32), 256>>>(Wk, wqkvh + 1024 * DM,    wqkvl + 1024 * DM,    DM, DM);
    wconv<<<dim3(32, 32), 256>>>(Wv, wqkvh + 2048 * DM,    wqkvl + 2048 * DM,    DM, DM);
    wconv<<<dim3(32, 32), 256>>>(Wo, woh, wol, DM, DM);
    wconv<<<dim3(128, 32), 256>>>(W1, w1h, w1l, DM, FF);   // [N=4096][K=1024]
    wconv<<<dim3(32, 128), 256>>>(W2, w2h, w2l, FF, DM);   // [N=1024][K=4096]

    // ---- LN1 ----
    ln_split<<<SQ, 256>>>(x, l1s, l1b, yh, yl);

    // ---- fused QKV: [4096,1024] @ [1024,3072] -> packed split qkv ----
    gemm_bf16<3><<<dim3(QKVN / 64, SQ / 128), 256, GSMEM>>>(
        yh, yl, wqkvh, wqkvl, bqkv, nullptr, nullptr, qkvh, qkvl, QKVN, QKVN, DM);

    // ---- attention ----
    attn_bf16<<<dim3(SQ / 128, NH), 256, ATTN_SMEM>>>(qkvh, qkvl, ctxh, ctxl);

    // ---- output projection + residual ----
    gemm_bf16<1><<<dim3(DM / 64, SQ / 128), 256, GSMEM>>>(
        ctxh, ctxl, woh, wol, bo, x, out, nullptr, nullptr, DM, DM, DM);

    // ---- LN2 ----
    ln_split<<<SQ, 256>>>(out, l2s, l2b, y2h, y2l);

    // ---- FFN1 + GELU -> split h ----
    gemm_bf16<2><<<dim3(FF / 64, SQ / 128), 256, GSMEM>>>(
        y2h, y2l, w1h, w1l, b1, nullptr, nullptr, hh, hl, FF, FF, DM);

    // ---- FFN2 + residual (C==R aliasing safe) ----
    gemm_bf16<1><<<dim3(DM / 64, SQ / 128), 256, GSMEM>>>(
        hh, hl, w2h, w2l, b2, out, out, nullptr, nullptr, DM, DM, FF);
}